// round 1
// baseline (speedup 1.0000x reference)
#include <cuda_runtime.h>
#include <math.h>

#define NN_MAX 50000
#define EE_MAX 800000

// ---------------- device scratch (no allocations allowed) ----------------
__device__ float  g_u[NN_MAX * 64];
__device__ float  g_v[NN_MAX * 64];
__device__ float  g_y2[(size_t)EE_MAX * 64];
__device__ float  g_xcat[NN_MAX * 192];
__device__ float  g_h1[NN_MAX * 256];
__device__ float  g_h2[NN_MAX * 64];
__device__ float  g_h3[NN_MAX * 32];
__device__ double g_sum[256];
__device__ double g_sq[256];
__device__ float  g_Wf[256 * 64];
__device__ float  g_bf[256];
__device__ float  g_Wd[64 * 64];
__device__ float  g_saff[64], g_taff[64];
__device__ int    g_deg[NN_MAX], g_rowptr[NN_MAX + 1], g_cursor[NN_MAX], g_adj[EE_MAX];

static inline int idivup(int a, int b) { return (a + b - 1) / b; }

// ---------------- CSR build ----------------
__global__ void count_kernel(const int* __restrict__ dst, int* __restrict__ deg, int E) {
    int e = blockIdx.x * 256 + threadIdx.x;
    if (e < E) atomicAdd(&deg[dst[e]], 1);
}

__global__ void scan_kernel(const int* __restrict__ deg, int* __restrict__ rowptr,
                            int* __restrict__ cursor, int N) {
    __shared__ int sh[1024];
    __shared__ int soff;
    int t = threadIdx.x;
    if (t == 0) { soff = 0; rowptr[0] = 0; }
    __syncthreads();
    for (int base = 0; base < N; base += 1024) {
        int x = (base + t < N) ? deg[base + t] : 0;
        sh[t] = x;
        __syncthreads();
        for (int d = 1; d < 1024; d <<= 1) {
            int vv = (t >= d) ? sh[t - d] : 0;
            __syncthreads();
            sh[t] += vv;
            __syncthreads();
        }
        int inc = sh[t] + soff;
        if (base + t < N) { rowptr[base + t + 1] = inc; cursor[base + t] = inc - x; }
        __syncthreads();
        if (t == 1023) soff = inc;
        __syncthreads();
    }
}

__global__ void scatter_kernel(const int* __restrict__ dst, int* __restrict__ cursor,
                               int* __restrict__ adj, int E) {
    int e = blockIdx.x * 256 + threadIdx.x;
    if (e < E) {
        int d = dst[e];
        int pos = atomicAdd(&cursor[d], 1);
        adj[pos] = e;
    }
}

// ---------------- W_top - W_bot prep ----------------
__global__ void wdiff_kernel(const float* __restrict__ Wa, float* __restrict__ Wd, int D) {
    int idx = blockIdx.x * 256 + threadIdx.x;
    if (idx < D * 64) Wd[idx] = Wa[idx] - Wa[D * 64 + idx];
}

// ---------------- generic tiled GEMM: Y = [relu](X@W + b), optional BN stats ----------------
// X: [R x K] row stride ldx; W: [K x CO] row stride ldw; Y: [R x CO] row stride ldy
__global__ void gemm_kernel(const float* __restrict__ X, int ldx, int R, int K,
                            const float* __restrict__ W, int ldw, int CO,
                            const float* __restrict__ bias,
                            float* __restrict__ Y, int ldy,
                            int do_relu, int do_stats,
                            double* __restrict__ gsum, double* __restrict__ gsq) {
    __shared__ float Xs[16 * 68];  // [k][r]
    __shared__ float Ws[16 * 68];  // [k][c]
    __shared__ float csum[64], csq[64];
    int t = threadIdx.x;
    int tx = t & 15, ty = t >> 4;
    int r0 = blockIdx.x * 64;
    int c0 = blockIdx.y * 64;
    if (do_stats && t < 64) { csum[t] = 0.f; csq[t] = 0.f; }
    float acc[4][4];
#pragma unroll
    for (int i = 0; i < 4; i++)
#pragma unroll
        for (int j = 0; j < 4; j++) acc[i][j] = 0.f;

    for (int kc = 0; kc < K; kc += 16) {
#pragma unroll
        for (int idx = t; idx < 64 * 16; idx += 256) {
            int r = idx >> 4, c = idx & 15;
            int gr = r0 + r, gk = kc + c;
            float vv = 0.f;
            if (gr < R && gk < K) vv = X[(size_t)gr * ldx + gk];
            Xs[c * 68 + r] = vv;
        }
#pragma unroll
        for (int idx = t; idx < 16 * 64; idx += 256) {
            int k = idx >> 6, c = idx & 63;
            int gk = kc + k, gc = c0 + c;
            float vv = 0.f;
            if (gk < K && gc < CO) vv = W[(size_t)gk * ldw + gc];
            Ws[k * 68 + c] = vv;
        }
        __syncthreads();
#pragma unroll
        for (int k = 0; k < 16; k++) {
            float4 e4 = *(const float4*)&Xs[k * 68 + ty * 4];
            float4 w4 = *(const float4*)&Ws[k * 68 + tx * 4];
            acc[0][0] += e4.x * w4.x; acc[0][1] += e4.x * w4.y; acc[0][2] += e4.x * w4.z; acc[0][3] += e4.x * w4.w;
            acc[1][0] += e4.y * w4.x; acc[1][1] += e4.y * w4.y; acc[1][2] += e4.y * w4.z; acc[1][3] += e4.y * w4.w;
            acc[2][0] += e4.z * w4.x; acc[2][1] += e4.z * w4.y; acc[2][2] += e4.z * w4.z; acc[2][3] += e4.z * w4.w;
            acc[3][0] += e4.w * w4.x; acc[3][1] += e4.w * w4.y; acc[3][2] += e4.w * w4.z; acc[3][3] += e4.w * w4.w;
        }
        __syncthreads();
    }

    float ps[4] = {0.f, 0.f, 0.f, 0.f}, pq[4] = {0.f, 0.f, 0.f, 0.f};
#pragma unroll
    for (int i = 0; i < 4; i++) {
        int gr = r0 + ty * 4 + i;
        if (gr >= R) continue;
#pragma unroll
        for (int j = 0; j < 4; j++) {
            int gc = c0 + tx * 4 + j;
            if (gc >= CO) continue;
            float vv = acc[i][j];
            if (bias) vv += bias[gc];
            if (do_relu) vv = fmaxf(vv, 0.f);
            Y[(size_t)gr * ldy + gc] = vv;
            ps[j] += vv; pq[j] += vv * vv;
        }
    }
    if (do_stats) {
        __syncthreads();
#pragma unroll
        for (int j = 0; j < 4; j++) {
            atomicAdd(&csum[tx * 4 + j], ps[j]);
            atomicAdd(&csq[tx * 4 + j], pq[j]);
        }
        __syncthreads();
        if (t < 64 && c0 + t < CO) {
            atomicAdd(&gsum[c0 + t], (double)csum[t]);
            atomicAdd(&gsq[c0 + t], (double)csq[t]);
        }
    }
}

// ---------------- edge stats pass: y1 = relu(u[dst]+v[src]+ba), accumulate stats ----------------
__global__ void edge_stats_kernel(const float* __restrict__ u, const float* __restrict__ v,
                                  const int* __restrict__ src, const int* __restrict__ dst,
                                  const float* __restrict__ ba,
                                  double* __restrict__ gsum, double* __restrict__ gsq, int E) {
    __shared__ float csum[64], csq[64];
    __shared__ int sidx[128], didx[128];
    int t = threadIdx.x;
    int e0 = blockIdx.x * 128;
    int ne = min(128, E - e0);
    if (t < ne) { sidx[t] = src[e0 + t]; didx[t] = dst[e0 + t]; }
    if (t < 64) { csum[t] = 0.f; csq[t] = 0.f; }
    __syncthreads();
    int c = t & 63, eg = t >> 6;
    float bac = ba[c];
    float ps = 0.f, pq = 0.f;
    for (int e = eg; e < ne; e += 4) {
        float val = u[(size_t)didx[e] * 64 + c] + v[(size_t)sidx[e] * 64 + c] + bac;
        val = fmaxf(val, 0.f);
        ps += val; pq += val * val;
    }
    atomicAdd(&csum[c], ps);
    atomicAdd(&csq[c], pq);
    __syncthreads();
    if (t < 64) {
        atomicAdd(&gsum[t], (double)csum[t]);
        atomicAdd(&gsq[t], (double)csq[t]);
    }
}

// ---------------- BN fold: s,t from stats; fold into next linear or export affine ----------------
__global__ void fold_kernel(double* __restrict__ gsum, double* __restrict__ gsq, double count,
                            const float* __restrict__ gamma, const float* __restrict__ beta, int CH,
                            const float* __restrict__ Wn, const float* __restrict__ bn_, int COn,
                            float* __restrict__ Wf, float* __restrict__ bf,
                            float* __restrict__ saff, float* __restrict__ taff, int mode) {
    __shared__ float ss[256], tt[256];
    int t = threadIdx.x;
    if (t < CH) {
        double mu = gsum[t] / count;
        double var = gsq[t] / count - mu * mu;
        if (var < 0.0) var = 0.0;
        float sc = gamma[t] * rsqrtf((float)var + 1e-5f);
        ss[t] = sc;
        tt[t] = beta[t] - (float)mu * sc;
        gsum[t] = 0.0; gsq[t] = 0.0;
    }
    __syncthreads();
    if (mode == 1) {
        if (t < CH) { saff[t] = ss[t]; taff[t] = tt[t]; }
        return;
    }
    for (int idx = t; idx < CH * COn; idx += 256)
        Wf[idx] = ss[idx / COn] * Wn[idx];
    if (t < COn) {
        float a = bn_[t];
        for (int c = 0; c < CH; c++) a += tt[c] * Wn[c * COn + t];
        bf[t] = a;
    }
}

// ---------------- per-edge GEMM B: y2 = relu( relu(u[dst]+v[src]+ba) @ Wf + bf ), stats ----------------
#define EDGEB_SMEM ((128 * 65 + 64 * 64) * 4)
__global__ void edge_gemm_B_kernel(const float* __restrict__ u, const float* __restrict__ v,
                                   const int* __restrict__ src, const int* __restrict__ dst,
                                   const float* __restrict__ ba,
                                   const float* __restrict__ Wf, const float* __restrict__ bf,
                                   float* __restrict__ y2,
                                   double* __restrict__ gsum, double* __restrict__ gsq, int E) {
    extern __shared__ float dyn[];
    float* y1s = dyn;              // [128][65]
    float* Ws = dyn + 128 * 65;    // [64][64]
    __shared__ int sidx[128], didx[128];
    __shared__ float bas[64], bfs[64], csum[64], csq[64];
    int t = threadIdx.x;
    int e0 = blockIdx.x * 128;
    int ne = min(128, E - e0);
    if (t < ne) { sidx[t] = src[e0 + t]; didx[t] = dst[e0 + t]; }
    if (t < 64) { bas[t] = ba[t]; bfs[t] = bf[t]; csum[t] = 0.f; csq[t] = 0.f; }
    for (int idx = t; idx < 64 * 64; idx += 256) Ws[idx] = Wf[idx];
    __syncthreads();
    for (int idx = t; idx < 128 * 64; idx += 256) {
        int e = idx >> 6, c = idx & 63;
        float val = 0.f;
        if (e < ne)
            val = fmaxf(u[(size_t)didx[e] * 64 + c] + v[(size_t)sidx[e] * 64 + c] + bas[c], 0.f);
        y1s[e * 65 + c] = val;
    }
    __syncthreads();
    int tx = t & 15, ty = t >> 4;
    float acc[8][4];
#pragma unroll
    for (int i = 0; i < 8; i++)
#pragma unroll
        for (int j = 0; j < 4; j++) acc[i][j] = 0.f;
#pragma unroll 16
    for (int k = 0; k < 64; k++) {
        float4 w4 = *(const float4*)&Ws[k * 64 + tx * 4];
#pragma unroll
        for (int i = 0; i < 8; i++) {
            float ev = y1s[(ty * 8 + i) * 65 + k];
            acc[i][0] += ev * w4.x;
            acc[i][1] += ev * w4.y;
            acc[i][2] += ev * w4.z;
            acc[i][3] += ev * w4.w;
        }
    }
    float ps[4] = {0.f, 0.f, 0.f, 0.f}, pq[4] = {0.f, 0.f, 0.f, 0.f};
#pragma unroll
    for (int i = 0; i < 8; i++) {
        int e = ty * 8 + i;
        if (e < ne) {
            float4 r;
            r.x = fmaxf(acc[i][0] + bfs[tx * 4 + 0], 0.f);
            r.y = fmaxf(acc[i][1] + bfs[tx * 4 + 1], 0.f);
            r.z = fmaxf(acc[i][2] + bfs[tx * 4 + 2], 0.f);
            r.w = fmaxf(acc[i][3] + bfs[tx * 4 + 3], 0.f);
            *(float4*)&y2[((size_t)(e0 + e)) * 64 + tx * 4] = r;
            ps[0] += r.x; pq[0] += r.x * r.x;
            ps[1] += r.y; pq[1] += r.y * r.y;
            ps[2] += r.z; pq[2] += r.z * r.z;
            ps[3] += r.w; pq[3] += r.w * r.w;
        }
    }
#pragma unroll
    for (int j = 0; j < 4; j++) {
        atomicAdd(&csum[tx * 4 + j], ps[j]);
        atomicAdd(&csq[tx * 4 + j], pq[j]);
    }
    __syncthreads();
    if (t < 64) {
        atomicAdd(&gsum[t], (double)csum[t]);
        atomicAdd(&gsq[t], (double)csq[t]);
    }
}

// ---------------- CSR max-aggregation with post-affine (sign-aware), zero-fill isolated ----------------
__global__ void agg_kernel(const float* __restrict__ y2, const int* __restrict__ rowptr,
                           const int* __restrict__ adj,
                           const float* __restrict__ s, const float* __restrict__ tt,
                           float* __restrict__ xcat, int col_off, int N) {
    int warp = (blockIdx.x * blockDim.x + threadIdx.x) >> 5;
    int lane = threadIdx.x & 31;
    if (warp >= N) return;
    int beg = rowptr[warp], end = rowptr[warp + 1];
    float mx0 = -3.4e38f, mx1 = -3.4e38f, mn0 = 3.4e38f, mn1 = 3.4e38f;
    for (int p = beg; p < end; p++) {
        int e = adj[p];
        float2 vv = *(const float2*)&y2[(size_t)e * 64 + lane * 2];
        mx0 = fmaxf(mx0, vv.x); mx1 = fmaxf(mx1, vv.y);
        mn0 = fminf(mn0, vv.x); mn1 = fminf(mn1, vv.y);
    }
    int c0 = lane * 2, c1 = c0 + 1;
    float s0 = s[c0], s1 = s[c1], t0 = tt[c0], t1 = tt[c1];
    float r0 = 0.f, r1 = 0.f;
    if (end > beg) {
        r0 = (s0 >= 0.f) ? (s0 * mx0 + t0) : (s0 * mn0 + t0);
        r1 = (s1 >= 0.f) ? (s1 * mx1 + t1) : (s1 * mn1 + t1);
    }
    xcat[(size_t)warp * 192 + col_off + c0] = r0;
    xcat[(size_t)warp * 192 + col_off + c1] = r1;
}

// ---------------- final: logits = h3 @ Wf + bf, log_softmax ----------------
__global__ void final_kernel(const float* __restrict__ h3, const float* __restrict__ Wf,
                             const float* __restrict__ bf, float* __restrict__ out, int N) {
    __shared__ float Ws[32 * 24];
    __shared__ float bs[24];
    __shared__ float hs[256 * 33];
    int t = threadIdx.x;
    for (int idx = t; idx < 32 * 24; idx += 256) Ws[idx] = Wf[idx];
    if (t < 24) bs[t] = bf[t];
    int n0 = blockIdx.x * 256;
    int cnt = min(256, N - n0);
    for (int idx = t; idx < cnt * 32; idx += 256) {
        int n = idx >> 5, c = idx & 31;
        hs[n * 33 + c] = h3[(size_t)(n0 + n) * 32 + c];
    }
    __syncthreads();
    float l[24];
    if (t < cnt) {
        float m = -3.4e38f;
#pragma unroll
        for (int j = 0; j < 24; j++) {
            float a = bs[j];
#pragma unroll
            for (int k = 0; k < 32; k++) a += hs[t * 33 + k] * Ws[k * 24 + j];
            l[j] = a;
            m = fmaxf(m, a);
        }
        float sum = 0.f;
#pragma unroll
        for (int j = 0; j < 24; j++) sum += __expf(l[j] - m);
        float lse = m + __logf(sum);
#pragma unroll
        for (int j = 0; j < 24; j++) l[j] -= lse;
    }
    __syncthreads();
    if (t < cnt) {
#pragma unroll
        for (int j = 0; j < 24; j++) hs[t * 33 + j] = l[j];
    }
    __syncthreads();
    for (int idx = t; idx < cnt * 24; idx += 256) {
        int n = idx / 24, j = idx % 24;
        out[(size_t)(n0 + n) * 24 + j] = hs[n * 33 + j];
    }
}

// ---------------- host orchestration ----------------
extern "C" void kernel_launch(void* const* d_in, const int* in_sizes, int n_in,
                              void* d_out, int out_size) {
    const float* x    = (const float*)d_in[0];
    const float* W1a  = (const float*)d_in[1];
    const float* b1a  = (const float*)d_in[2];
    const float* g1a  = (const float*)d_in[3];
    const float* be1a = (const float*)d_in[4];
    const float* W1b  = (const float*)d_in[5];
    const float* b1b  = (const float*)d_in[6];
    const float* g1b  = (const float*)d_in[7];
    const float* be1b = (const float*)d_in[8];
    const float* Wa   = (const float*)d_in[9];
    const float* ba   = (const float*)d_in[10];
    const float* ga   = (const float*)d_in[11];
    const float* bea  = (const float*)d_in[12];
    const float* Wb   = (const float*)d_in[13];
    const float* bb   = (const float*)d_in[14];
    const float* gb   = (const float*)d_in[15];
    const float* beb  = (const float*)d_in[16];
    const float* Wl   = (const float*)d_in[17];
    const float* bl   = (const float*)d_in[18];
    const float* gl   = (const float*)d_in[19];
    const float* bel  = (const float*)d_in[20];
    const float* Wm1  = (const float*)d_in[21];
    const float* bm1  = (const float*)d_in[22];
    const float* gm1  = (const float*)d_in[23];
    const float* bem1 = (const float*)d_in[24];
    const float* Wm2  = (const float*)d_in[25];
    const float* bm2  = (const float*)d_in[26];
    const float* gm2  = (const float*)d_in[27];
    const float* bem2 = (const float*)d_in[28];
    const float* Wo   = (const float*)d_in[29];
    const float* bo   = (const float*)d_in[30];
    const int*   eidx = (const int*)d_in[31];

    int N = in_sizes[0] / 6;
    int E = in_sizes[31] / 2;
    const int* src = eidx;
    const int* dst = eidx + E;

    float *u, *v, *y2, *xcat, *h1, *h2, *h3, *Wf, *bf, *Wd, *saff, *taff;
    double *gsum, *gsq;
    int *deg, *rowptr, *cursor, *adj;
    cudaGetSymbolAddress((void**)&u, g_u);
    cudaGetSymbolAddress((void**)&v, g_v);
    cudaGetSymbolAddress((void**)&y2, g_y2);
    cudaGetSymbolAddress((void**)&xcat, g_xcat);
    cudaGetSymbolAddress((void**)&h1, g_h1);
    cudaGetSymbolAddress((void**)&h2, g_h2);
    cudaGetSymbolAddress((void**)&h3, g_h3);
    cudaGetSymbolAddress((void**)&Wf, g_Wf);
    cudaGetSymbolAddress((void**)&bf, g_bf);
    cudaGetSymbolAddress((void**)&Wd, g_Wd);
    cudaGetSymbolAddress((void**)&saff, g_saff);
    cudaGetSymbolAddress((void**)&taff, g_taff);
    cudaGetSymbolAddress((void**)&gsum, g_sum);
    cudaGetSymbolAddress((void**)&gsq, g_sq);
    cudaGetSymbolAddress((void**)&deg, g_deg);
    cudaGetSymbolAddress((void**)&rowptr, g_rowptr);
    cudaGetSymbolAddress((void**)&cursor, g_cursor);
    cudaGetSymbolAddress((void**)&adj, g_adj);

    cudaFuncSetAttribute(edge_gemm_B_kernel, cudaFuncAttributeMaxDynamicSharedMemorySize, EDGEB_SMEM);

    cudaMemsetAsync(gsum, 0, 256 * sizeof(double));
    cudaMemsetAsync(gsq, 0, 256 * sizeof(double));
    cudaMemsetAsync(deg, 0, N * sizeof(int));

    // CSR by dst
    count_kernel<<<idivup(E, 256), 256>>>(dst, deg, E);
    scan_kernel<<<1, 1024>>>(deg, rowptr, cursor, N);
    scatter_kernel<<<idivup(E, 256), 256>>>(dst, cursor, adj, E);

    struct ConvP {
        const float* xin; int ldx; int K;
        const float *Wa_, *ba_, *ga_, *bea_, *Wb_, *bb_, *gb_, *beb_;
    };
    ConvP convs[3] = {
        { x,         6,   6,  W1a,          b1a,     g1a,     be1a,     W1b,          b1b,     g1b,     be1b     },
        { xcat,      192, 64, Wa,           ba,      ga,      bea,      Wb,           bb,      gb,      beb      },
        { xcat + 64, 192, 64, Wa + 128 * 64, ba + 64, ga + 64, bea + 64, Wb + 64 * 64, bb + 64, gb + 64, beb + 64 },
    };

    for (int cv = 0; cv < 3; cv++) {
        const ConvP& P = convs[cv];
        wdiff_kernel<<<idivup(P.K * 64, 256), 256>>>(P.Wa_, Wd, P.K);
        dim3 gg(idivup(N, 64), 1);
        gemm_kernel<<<gg, 256>>>(P.xin, P.ldx, N, P.K, Wd, 64, 64, (const float*)0,
                                 u, 64, 0, 0, (double*)0, (double*)0);
        gemm_kernel<<<gg, 256>>>(P.xin, P.ldx, N, P.K, P.Wa_ + (size_t)P.K * 64, 64, 64, (const float*)0,
                                 v, 64, 0, 0, (double*)0, (double*)0);
        edge_stats_kernel<<<idivup(E, 128), 256>>>(u, v, src, dst, P.ba_, gsum, gsq, E);
        fold_kernel<<<1, 256>>>(gsum, gsq, (double)E, P.ga_, P.bea_, 64,
                                P.Wb_, P.bb_, 64, Wf, bf, (float*)0, (float*)0, 0);
        edge_gemm_B_kernel<<<idivup(E, 128), 256, EDGEB_SMEM>>>(u, v, src, dst, P.ba_,
                                                                Wf, bf, y2, gsum, gsq, E);
        fold_kernel<<<1, 256>>>(gsum, gsq, (double)E, P.gb_, P.beb_, 64,
                                (const float*)0, (const float*)0, 0, (float*)0, (float*)0, saff, taff, 1);
        agg_kernel<<<idivup(N, 8), 256>>>(y2, rowptr, adj, saff, taff, xcat, cv * 64, N);
    }

    // MLP head
    gemm_kernel<<<dim3(idivup(N, 64), 4), 256>>>(xcat, 192, N, 192, Wl, 256, 256, bl,
                                                 h1, 256, 1, 1, gsum, gsq);
    fold_kernel<<<1, 256>>>(gsum, gsq, (double)N, gl, bel, 256, Wm1, bm1, 64, Wf, bf, (float*)0, (float*)0, 0);
    gemm_kernel<<<dim3(idivup(N, 64), 1), 256>>>(h1, 256, N, 256, Wf, 64, 64, bf,
                                                 h2, 64, 1, 1, gsum, gsq);
    fold_kernel<<<1, 256>>>(gsum, gsq, (double)N, gm1, bem1, 64, Wm2, bm2, 32, Wf, bf, (float*)0, (float*)0, 0);
    gemm_kernel<<<dim3(idivup(N, 64), 1), 256>>>(h2, 64, N, 64, Wf, 32, 32, bf,
                                                 h3, 32, 1, 1, gsum, gsq);
    fold_kernel<<<1, 256>>>(gsum, gsq, (double)N, gm2, bem2, 32, Wo, bo, 24, Wf, bf, (float*)0, (float*)0, 0);
    final_kernel<<<idivup(N, 256), 256>>>(h3, Wf, bf, (float*)d_out, N);
}